// round 6
// baseline (speedup 1.0000x reference)
#include <cuda_runtime.h>

typedef unsigned long long u64t;

// ---- packed f32x2 helpers (sm_103a) ----
__device__ __forceinline__ u64t pack2(float x, float y){
    u64t r; asm("mov.b64 %0,{%1,%2};" : "=l"(r) : "f"(x), "f"(y)); return r;
}
__device__ __forceinline__ u64t pack2d(float x){
    u64t r; asm("mov.b64 %0,{%1,%1};" : "=l"(r) : "f"(x)); return r;
}
__device__ __forceinline__ float2 unpack2(u64t a){
    float2 r; asm("mov.b64 {%0,%1},%2;" : "=f"(r.x), "=f"(r.y) : "l"(a)); return r;
}
__device__ __forceinline__ u64t fma2_(u64t a, u64t b, u64t c){
    u64t d; asm("fma.rn.f32x2 %0,%1,%2,%3;" : "=l"(d) : "l"(a), "l"(b), "l"(c)); return d;
}
__device__ __forceinline__ u64t mul2_(u64t a, u64t b){
    u64t d; asm("mul.rn.f32x2 %0,%1,%2;" : "=l"(d) : "l"(a), "l"(b)); return d;
}
__device__ __forceinline__ u64t add2_(u64t a, u64t b){
    u64t d; asm("add.rn.f32x2 %0,%1,%2;" : "=l"(d) : "l"(a), "l"(b)); return d;
}

#define NB     32      // batches
#define NI     4096    // input capsules
#define NO     32      // output capsules
#define CI     32      // i per chunk
#define NCHUNK 128     // NI / CI
#define BG     4       // batch groups (8 warps/block x 4 groups = 32 batches)
#define EL     (NB * NO * 16)      // 16384 output elements
#define PSLAB  EL                  // floats per partial slab

// scratch (static device globals — no allocations)
__device__ __align__(16) u64t  g_wt[NI * 8 * NO];        // transposed W, z-paired: [i][q][o], 8 MB
__device__ __align__(16) float g_part[NCHUNK * PSLAB];   // 8 MB partials: [chunk][b][o][16]
__device__ __align__(16) float g_part2[8 * EL];          // 512 KB stage-2 partials
__device__ __align__(16) float g_v[EL];                  // v for logits this pass
__device__ __align__(16) float g_vsum[EL];               // running sum of v's

// ---------------------------------------------------------------------------
// Transpose W: w[o][i][4][4] -> Wt[i][q][o] (u64 z-pairs, q = y*2 + z/2).
// ---------------------------------------------------------------------------
__global__ __launch_bounds__(256) void wt_kernel(const float* __restrict__ w)
{
    int idx = blockIdx.x * 256 + threadIdx.x;      // (i*8 + q)*32 + o
    int o = idx & 31;
    int q = (idx >> 5) & 7;
    int i = idx >> 8;
    const float2* src = (const float2*)(w + ((size_t)o * NI + i) * 16) + q;
    float2 v = __ldg(src);
    g_wt[idx] = pack2(v.x, v.y);
}

// ---------------------------------------------------------------------------
// Pass kernel: grid (NCHUNK, BG), block 256 = 8 warps.
// Warp owns (batch b = g*8 + warp, chunk c): lane = o, loops all 32 i.
// Poses staged in shared memory pre-duplicated to f32x2 (u64) per block:
// inner loop does 16 broadcast LDS.64 per i instead of 16 SHFL + 16 MOV.
// Warp exclusively writes g_part[c][b][o][16]; no cross-warp reduce.
// ---------------------------------------------------------------------------
template<bool FIRST>
__global__ __launch_bounds__(256, 2) void pass_kernel(const float* __restrict__ poses)
{
    __shared__ u64t Ps[8][CI * 16];   // 32 KB: [batch-warp][i*16+k], duplicated

    const int tid  = threadIdx.x;
    const int lane = tid & 31;
    const int warp = tid >> 5;
    const int c    = blockIdx.x;
    const int b    = blockIdx.y * 8 + warp;
    const int o    = lane;

    // stage: thread (tb = warp, tl = lane) loads the 16 floats of pose
    // (batch blockIdx.y*8+tb, capsule c*32+tl) and stores duplicated u64s.
    {
        const float4* pp = (const float4*)(poses + ((size_t)b * NI + (size_t)c * CI + lane) * 16);
        #pragma unroll
        for (int x = 0; x < 4; x++) {
            float4 t = pp[x];
            Ps[warp][lane * 16 + 4 * x + 0] = pack2d(t.x);
            Ps[warp][lane * 16 + 4 * x + 1] = pack2d(t.y);
            Ps[warp][lane * 16 + 4 * x + 2] = pack2d(t.z);
            Ps[warp][lane * 16 + 4 * x + 3] = pack2d(t.w);
        }
    }
    __syncthreads();

    // v for the logit dot-product (passes 2,3): per-lane (b, o)
    u64t vreg[8];
    if (!FIRST) {
        const float4* gv = (const float4*)(g_v + ((size_t)b * NO + o) * 16);
        #pragma unroll
        for (int x = 0; x < 4; x++) {
            float4 a = __ldg(gv + x);
            vreg[2 * x]     = pack2(a.x, a.y);
            vreg[2 * x + 1] = pack2(a.z, a.w);
        }
    }

    u64t sacc[8];
    #pragma unroll
    for (int q = 0; q < 8; q++) sacc[q] = 0ull;

    const u64t* wt  = g_wt + ((size_t)c * CI) * 8 * 32 + o;
    const u64t* myP = Ps[warp];

    #pragma unroll 2
    for (int i = 0; i < CI; i++) {
        // W row for (o, i): 8 coalesced LDG.64 (L1-hot across the 8 warps)
        u64t Wp[8];
        #pragma unroll
        for (int q = 0; q < 8; q++) Wp[q] = wt[(i * 8 + q) * 32];

        // pose of capsule i: 16 broadcast LDS.64 (already duplicated)
        const u64t* Pi = myP + i * 16;

        // votes V[x][zpair] = sum_y P[x][y] * W[y][zpair]
        u64t V[8];
        #pragma unroll
        for (int x = 0; x < 4; x++) {
            u64t p0 = Pi[4 * x];
            V[2 * x]     = mul2_(p0, Wp[0]);
            V[2 * x + 1] = mul2_(p0, Wp[1]);
            #pragma unroll
            for (int y = 1; y < 4; y++) {
                u64t p = Pi[4 * x + y];
                V[2 * x]     = fma2_(p, Wp[2 * y],     V[2 * x]);
                V[2 * x + 1] = fma2_(p, Wp[2 * y + 1], V[2 * x + 1]);
            }
        }

        if (FIRST) {
            // coupling uniform 1/32 (softmax of zeros); scale applied in rsB
            #pragma unroll
            for (int q = 0; q < 8; q++) sacc[q] = add2_(sacc[q], V[q]);
        } else {
            // logit = <V, v>, softmax over o (= lanes)
            u64t d = mul2_(V[0], vreg[0]);
            #pragma unroll
            for (int q = 1; q < 8; q++) d = fma2_(V[q], vreg[q], d);
            float2 dd = unpack2(d);
            float e = __expf(dd.x + dd.y);     // logits are O(1); no max-shift needed
            float den = e;
            #pragma unroll
            for (int sh = 16; sh > 0; sh >>= 1)
                den += __shfl_xor_sync(0xffffffffu, den, sh);
            float cc = __fdividef(e, den);
            u64t cp = pack2d(cc);
            #pragma unroll
            for (int q = 0; q < 8; q++) sacc[q] = fma2_(cp, V[q], sacc[q]);
        }
    }

    // sole owner of g_part[c][b][o][0..15]
    float4* gp = (float4*)(g_part + (((size_t)c * NB + b) * NO + o) * 16);
    #pragma unroll
    for (int x = 0; x < 4; x++) {
        float2 a  = unpack2(sacc[2 * x]);
        float2 bb = unpack2(sacc[2 * x + 1]);
        gp[x] = make_float4(a.x, a.y, bb.x, bb.y);
    }
}

// ---------------------------------------------------------------------------
// rsA: reduce 128 slabs -> 8 partials per element. 131072 threads, coalesced.
// ---------------------------------------------------------------------------
__global__ __launch_bounds__(256) void rsA_kernel()
{
    int idx = blockIdx.x * 256 + threadIdx.x;   // 0 .. 8*EL-1
    int p = idx >> 14;                          // partial group 0..7
    int t = idx & (EL - 1);                     // element
    float s = 0.f;
    const float* gp = g_part + (size_t)(p * 16) * PSLAB + t;
    #pragma unroll
    for (int j = 0; j < 16; j++) s += gp[(size_t)j * PSLAB];
    g_part2[(size_t)p * EL + t] = s;
}

// ---------------------------------------------------------------------------
// rsB: reduce 8 partials + squash. 16384 threads; 16 lanes = one (b,o).
// PHASE 0: v0 -> g_v, g_vsum.  PHASE 1: g_v = v0 + v1.  PHASE 2: write output.
// ---------------------------------------------------------------------------
template<int PHASE>
__global__ __launch_bounds__(256) void rsB_kernel(float* __restrict__ out)
{
    int t = blockIdx.x * 256 + threadIdx.x;     // t = b*512 + o*16 + k
    float s = 0.f;
    #pragma unroll
    for (int p = 0; p < 8; p++) s += g_part2[(size_t)p * EL + t];
    if (PHASE == 0) s *= (1.0f / 32.0f);        // uniform coupling on iter 0

    float n2 = s * s;
    #pragma unroll
    for (int sh = 1; sh < 16; sh <<= 1)
        n2 += __shfl_xor_sync(0xffffffffu, n2, sh);   // sum over 16 pose elems

    float n = sqrtf(n2 + 1e-12f);
    float f = n2 / ((1.0f + n2) * n);
    float v = s * f;

    if (PHASE == 0)      { g_v[t] = v; g_vsum[t] = v; }
    else if (PHASE == 1) { g_v[t] = g_vsum[t] + v; }
    else {
        out[t] = v;                                     // capsule_poses [B,O,4,4]
        if ((t & 15) == 0)
            out[EL + (t >> 4)] = sqrtf(n2 * f * f + 1e-12f);  // activations
    }
}

extern "C" void kernel_launch(void* const* d_in, const int* in_sizes, int n_in,
                              void* d_out, int out_size)
{
    const float* poses = (const float*)d_in[0];
    // d_in[1] = input_activations — unused by the reference math
    const float* w     = (const float*)d_in[2];
    float* out = (float*)d_out;

    dim3 pgrid(NCHUNK, BG);

    wt_kernel<<<NI * 8 * NO / 256, 256>>>(w);

    pass_kernel<true ><<<pgrid, 256>>>(poses);
    rsA_kernel<<<8 * EL / 256, 256>>>();
    rsB_kernel<0><<<EL / 256, 256>>>(nullptr);

    pass_kernel<false><<<pgrid, 256>>>(poses);
    rsA_kernel<<<8 * EL / 256, 256>>>();
    rsB_kernel<1><<<EL / 256, 256>>>(nullptr);

    pass_kernel<false><<<pgrid, 256>>>(poses);
    rsA_kernel<<<8 * EL / 256, 256>>>();
    rsB_kernel<2><<<EL / 256, 256>>>(out);
}

// round 8
// speedup vs baseline: 1.0335x; 1.0335x over previous
#include <cuda_runtime.h>

typedef unsigned long long u64t;

// ---- packed f32x2 helpers (sm_103a) ----
__device__ __forceinline__ u64t pack2(float x, float y){
    u64t r; asm("mov.b64 %0,{%1,%2};" : "=l"(r) : "f"(x), "f"(y)); return r;
}
__device__ __forceinline__ u64t pack2d(float x){
    u64t r; asm("mov.b64 %0,{%1,%1};" : "=l"(r) : "f"(x)); return r;
}
__device__ __forceinline__ float2 unpack2(u64t a){
    float2 r; asm("mov.b64 {%0,%1},%2;" : "=f"(r.x), "=f"(r.y) : "l"(a)); return r;
}
__device__ __forceinline__ u64t fma2_(u64t a, u64t b, u64t c){
    u64t d; asm("fma.rn.f32x2 %0,%1,%2,%3;" : "=l"(d) : "l"(a), "l"(b), "l"(c)); return d;
}
__device__ __forceinline__ u64t mul2_(u64t a, u64t b){
    u64t d; asm("mul.rn.f32x2 %0,%1,%2;" : "=l"(d) : "l"(a), "l"(b)); return d;
}
__device__ __forceinline__ u64t add2_(u64t a, u64t b){
    u64t d; asm("add.rn.f32x2 %0,%1,%2;" : "=l"(d) : "l"(a), "l"(b)); return d;
}

#define NB     32                 // batches
#define NI     4096               // input capsules
#define NO     32                 // output capsules
#define NPAIR  (NI / 2)           // 2048 capsule pairs
#define CI     32                 // i per chunk
#define CP     (CI / 2)           // 16 pairs per chunk
#define NCHUNK (NI / CI)          // 128
#define BG     4                  // batch groups: 8 warps/block x 4 = 32 batches
#define EL     (NB * NO * 16)     // 16384 output elements
#define PSLAB  EL                 // floats per partial slab

// scratch (static device globals — no allocations)
__device__ __align__(16) u64t  g_wt2[NPAIR * 16 * NO];   // W i-paired: [IP][k][o], 8 MB
__device__ __align__(16) u64t  g_pp [NB * NPAIR * 16];   // poses i-paired: [b][IP][k], 8 MB
__device__ __align__(16) float g_part[NCHUNK * PSLAB];   // 8 MB partials: [chunk][b][o][16]
__device__ __align__(16) float g_part2[8 * EL];          // 512 KB stage-2 partials
__device__ __align__(16) float g_v[EL];                  // v for logits this pass
__device__ __align__(16) float g_vsum[EL];               // running sum of v's

// ---------------------------------------------------------------------------
// W prep: w[o][i][k] -> g_wt2[IP][k][o] = pack(w[o][2IP][k], w[o][2IP+1][k]).
// k = y*4+z. Coalesced writes.
// ---------------------------------------------------------------------------
__global__ __launch_bounds__(256) void wt2_kernel(const float* __restrict__ w)
{
    int idx = blockIdx.x * 256 + threadIdx.x;    // (IP*16 + k)*32 + o
    int o  = idx & 31;
    int k  = (idx >> 5) & 15;
    int ip = idx >> 9;
    const float* s0 = w + ((size_t)o * NI + 2 * ip) * 16 + k;
    g_wt2[idx] = pack2(__ldg(s0), __ldg(s0 + 16));
}

// ---------------------------------------------------------------------------
// Pose prep: poses[b][i][k] -> g_pp[b][IP][k] = pack(P[b][2IP][k], P[b][2IP+1][k]).
// k = x*4+y.
// ---------------------------------------------------------------------------
__global__ __launch_bounds__(256) void pp_kernel(const float* __restrict__ poses)
{
    int idx = blockIdx.x * 256 + threadIdx.x;    // (b*NPAIR + IP)*16 + k
    int k  = idx & 15;
    int ip = (idx >> 4) & (NPAIR - 1);
    int b  = idx >> 15;
    const float* s0 = poses + ((size_t)b * NI + 2 * ip) * 16 + k;
    g_pp[idx] = pack2(__ldg(s0), __ldg(s0 + 16));
}

// ---------------------------------------------------------------------------
// Pass body. Warp owns (batch b, chunk c): lane = o, loops over CP i-pairs.
// Everything packed over (i0,i1); zero operand duplication in the hot loop.
// PsW = this warp's private smem staging area (CP*16 u64).
// ---------------------------------------------------------------------------
template<bool FIRST>
__device__ __forceinline__ void pass_body(int c, int b, int lane, u64t* PsW)
{
    const int o = lane;

    // stage paired poses for (b, chunk c): CP*16 = 256 u64, warp-private
    {
        const u64t* src = g_pp + ((size_t)b * NPAIR + (size_t)c * CP) * 16;
        #pragma unroll
        for (int j = 0; j < 8; j++) PsW[lane + 32 * j] = src[lane + 32 * j];
    }
    __syncwarp();

    // v duplicated into both halves (same v multiplies both i0 and i1 votes)
    u64t vd[16];
    if (!FIRST) {
        const float4* gv4 = (const float4*)(g_v + ((size_t)b * NO + o) * 16);
        #pragma unroll
        for (int q = 0; q < 4; q++) {
            float4 a = __ldg(gv4 + q);
            vd[4 * q + 0] = pack2d(a.x);
            vd[4 * q + 1] = pack2d(a.y);
            vd[4 * q + 2] = pack2d(a.z);
            vd[4 * q + 3] = pack2d(a.w);
        }
    }

    u64t sacc[16];
    #pragma unroll
    for (int k = 0; k < 16; k++) sacc[k] = 0ull;

    const u64t* Wb = (const u64t*)g_wt2 + (size_t)c * CP * 16 * 32 + o;

    #pragma unroll 1
    for (int ip = 0; ip < CP; ip++) {
        // paired W row: 16 coalesced LDG.64 (L1-hot across the block's 8 warps)
        u64t Wk[16];
        #pragma unroll
        for (int k = 0; k < 16; k++) Wk[k] = __ldg(Wb + (ip * 16 + k) * 32);

        const u64t* Pp = PsW + ip * 16;   // 16 broadcast LDS.64 per pair

        if (FIRST) {
            // votes accumulate straight into sacc (uniform c=1/32 applied in rsB)
            #pragma unroll
            for (int y = 0; y < 4; y++)
                #pragma unroll
                for (int x = 0; x < 4; x++) {
                    u64t p = Pp[x * 4 + y];
                    #pragma unroll
                    for (int z = 0; z < 4; z++)
                        sacc[x * 4 + z] = fma2_(p, Wk[y * 4 + z], sacc[x * 4 + z]);
                }
        } else {
            // votes V[x*4+z] halves = (V_i0, V_i1)
            u64t V[16];
            #pragma unroll
            for (int x = 0; x < 4; x++) {
                u64t p0 = Pp[x * 4];
                #pragma unroll
                for (int z = 0; z < 4; z++) V[x * 4 + z] = mul2_(p0, Wk[z]);
            }
            #pragma unroll
            for (int y = 1; y < 4; y++)
                #pragma unroll
                for (int x = 0; x < 4; x++) {
                    u64t p = Pp[x * 4 + y];
                    #pragma unroll
                    for (int z = 0; z < 4; z++)
                        V[x * 4 + z] = fma2_(p, Wk[y * 4 + z], V[x * 4 + z]);
                }

            // both logits in one packed dot: halves = (<V_i0,v>, <V_i1,v>)
            u64t da = mul2_(V[0], vd[0]);
            u64t db = mul2_(V[1], vd[1]);
            #pragma unroll
            for (int k = 2; k < 16; k += 2) {
                da = fma2_(V[k],     vd[k],     da);
                db = fma2_(V[k + 1], vd[k + 1], db);
            }
            float2 dl = unpack2(add2_(da, db));

            // two independent softmaxes over o (= lanes), interleaved for ILP
            float e0 = __expf(dl.x), e1 = __expf(dl.y);
            float s0 = e0, s1 = e1;
            #pragma unroll
            for (int sh = 16; sh > 0; sh >>= 1) {
                s0 += __shfl_xor_sync(0xffffffffu, s0, sh);
                s1 += __shfl_xor_sync(0xffffffffu, s1, sh);
            }
            u64t cp = pack2(__fdividef(e0, s0), __fdividef(e1, s1));

            #pragma unroll
            for (int k = 0; k < 16; k++) sacc[k] = fma2_(cp, V[k], sacc[k]);
        }
    }

    // writeout: fold the (i0, i1) halves; sole owner of g_part[c][b][o][16]
    float4* gp = (float4*)(g_part + (((size_t)c * NB + b) * NO + o) * 16);
    #pragma unroll
    for (int x = 0; x < 4; x++) {
        float2 a0 = unpack2(sacc[x * 4 + 0]);
        float2 a1 = unpack2(sacc[x * 4 + 1]);
        float2 a2 = unpack2(sacc[x * 4 + 2]);
        float2 a3 = unpack2(sacc[x * 4 + 3]);
        gp[x] = make_float4(a0.x + a0.y, a1.x + a1.y, a2.x + a2.y, a3.x + a3.y);
    }
}

__global__ __launch_bounds__(256, 3) void pass1_kernel()
{
    __shared__ u64t Ps[8][CP * 16];   // 16 KB, warp-private slices
    int lane = threadIdx.x & 31, warp = threadIdx.x >> 5;
    pass_body<true>(blockIdx.x, blockIdx.y * 8 + warp, lane, Ps[warp]);
}

__global__ __launch_bounds__(256, 2) void pass23_kernel()
{
    __shared__ u64t Ps[8][CP * 16];
    int lane = threadIdx.x & 31, warp = threadIdx.x >> 5;
    pass_body<false>(blockIdx.x, blockIdx.y * 8 + warp, lane, Ps[warp]);
}

// ---------------------------------------------------------------------------
// rsA: reduce 128 slabs -> 8 partials per element. 131072 threads, coalesced.
// ---------------------------------------------------------------------------
__global__ __launch_bounds__(256) void rsA_kernel()
{
    int idx = blockIdx.x * 256 + threadIdx.x;   // 0 .. 8*EL-1
    int p = idx >> 14;                          // partial group 0..7
    int t = idx & (EL - 1);                     // element
    float s = 0.f;
    const float* gp = g_part + (size_t)(p * 16) * PSLAB + t;
    #pragma unroll
    for (int j = 0; j < 16; j++) s += gp[(size_t)j * PSLAB];
    g_part2[(size_t)p * EL + t] = s;
}

// ---------------------------------------------------------------------------
// rsB: reduce 8 partials + squash. 16384 threads; 16 lanes = one (b,o).
// PHASE 0: v0 -> g_v, g_vsum.  PHASE 1: g_v = v0 + v1.  PHASE 2: write output.
// ---------------------------------------------------------------------------
template<int PHASE>
__global__ __launch_bounds__(256) void rsB_kernel(float* __restrict__ out)
{
    int t = blockIdx.x * 256 + threadIdx.x;     // t = b*512 + o*16 + k
    float s = 0.f;
    #pragma unroll
    for (int p = 0; p < 8; p++) s += g_part2[(size_t)p * EL + t];
    if (PHASE == 0) s *= (1.0f / 32.0f);        // uniform coupling on iter 0

    float n2 = s * s;
    #pragma unroll
    for (int sh = 1; sh < 16; sh <<= 1)
        n2 += __shfl_xor_sync(0xffffffffu, n2, sh);   // sum over 16 pose elems

    float n = sqrtf(n2 + 1e-12f);
    float f = n2 / ((1.0f + n2) * n);
    float v = s * f;

    if (PHASE == 0)      { g_v[t] = v; g_vsum[t] = v; }
    else if (PHASE == 1) { g_v[t] = g_vsum[t] + v; }
    else {
        out[t] = v;                                     // capsule_poses [B,O,4,4]
        if ((t & 15) == 0)
            out[EL + (t >> 4)] = sqrtf(n2 * f * f + 1e-12f);  // activations
    }
}

extern "C" void kernel_launch(void* const* d_in, const int* in_sizes, int n_in,
                              void* d_out, int out_size)
{
    const float* poses = (const float*)d_in[0];
    // d_in[1] = input_activations — unused by the reference math
    const float* w     = (const float*)d_in[2];
    float* out = (float*)d_out;

    dim3 pgrid(NCHUNK, BG);

    wt2_kernel<<<NPAIR * 16 * NO / 256, 256>>>(w);
    pp_kernel <<<NB * NPAIR * 16 / 256, 256>>>(poses);

    pass1_kernel<<<pgrid, 256>>>();
    rsA_kernel<<<8 * EL / 256, 256>>>();
    rsB_kernel<0><<<EL / 256, 256>>>(nullptr);

    pass23_kernel<<<pgrid, 256>>>();
    rsA_kernel<<<8 * EL / 256, 256>>>();
    rsB_kernel<1><<<EL / 256, 256>>>(nullptr);

    pass23_kernel<<<pgrid, 256>>>();
    rsA_kernel<<<8 * EL / 256, 256>>>();
    rsB_kernel<2><<<EL / 256, 256>>>(out);
}

// round 10
// speedup vs baseline: 1.1774x; 1.1393x over previous
#include <cuda_runtime.h>

typedef unsigned long long u64t;

// ---- packed f32x2 helpers (sm_103a) ----
__device__ __forceinline__ u64t pack2(float x, float y){
    u64t r; asm("mov.b64 %0,{%1,%2};" : "=l"(r) : "f"(x), "f"(y)); return r;
}
__device__ __forceinline__ u64t pack2d(float x){
    u64t r; asm("mov.b64 %0,{%1,%1};" : "=l"(r) : "f"(x)); return r;
}
__device__ __forceinline__ float2 unpack2(u64t a){
    float2 r; asm("mov.b64 {%0,%1},%2;" : "=f"(r.x), "=f"(r.y) : "l"(a)); return r;
}
__device__ __forceinline__ u64t fma2_(u64t a, u64t b, u64t c){
    u64t d; asm("fma.rn.f32x2 %0,%1,%2,%3;" : "=l"(d) : "l"(a), "l"(b), "l"(c)); return d;
}
__device__ __forceinline__ u64t mul2_(u64t a, u64t b){
    u64t d; asm("mul.rn.f32x2 %0,%1,%2;" : "=l"(d) : "l"(a), "l"(b)); return d;
}
__device__ __forceinline__ u64t add2_(u64t a, u64t b){
    u64t d; asm("add.rn.f32x2 %0,%1,%2;" : "=l"(d) : "l"(a), "l"(b)); return d;
}

#define NB     32                 // batches
#define NI     4096               // input capsules
#define NO     32                 // output capsules
#define NPAIR  (NI / 2)           // 2048 capsule pairs
#define CI     32                 // i per chunk
#define CP     (CI / 2)           // 16 pairs per chunk
#define NCHUNK (NI / CI)          // 128
#define EL     (NB * NO * 16)     // 16384 output elements
#define PSLAB  EL                 // floats per partial slab

// scratch (static device globals — no allocations)
__device__ __align__(16) u64t  g_wt2[NPAIR * 16 * NO];   // W i-paired: [IP][k][o], 8 MB
__device__ __align__(16) u64t  g_pp [NB * NPAIR * 16];   // poses i-paired: [b][IP][k], 8 MB
__device__ __align__(16) float g_part[NCHUNK * PSLAB];   // 8 MB partials: [chunk][b][o][16]
__device__ __align__(16) float g_part2[8 * EL];          // 512 KB stage-2 partials
__device__ __align__(16) float g_v[EL];                  // v for logits this pass
__device__ __align__(16) float g_vsum[EL];               // running sum of v's

// ---------------------------------------------------------------------------
// Prep (one launch): blocks [0,4096) build g_wt2, blocks [4096,8192) build g_pp.
// g_wt2[(IP*16+k)*32+o] = pack(w[o][2IP][k], w[o][2IP+1][k]),  k = y*4+z
// g_pp [(b*NPAIR+IP)*16+k] = pack(P[b][2IP][k], P[b][2IP+1][k]), k = x*4+y
// ---------------------------------------------------------------------------
__global__ __launch_bounds__(256) void prep_kernel(const float* __restrict__ poses,
                                                   const float* __restrict__ w)
{
    int bid = blockIdx.x;
    int tid = threadIdx.x;
    if (bid < 4096) {
        int idx = bid * 256 + tid;                // (IP*16 + k)*32 + o
        int o  = idx & 31;
        int k  = (idx >> 5) & 15;
        int ip = idx >> 9;
        const float* s0 = w + ((size_t)o * NI + 2 * ip) * 16 + k;
        g_wt2[idx] = pack2(__ldg(s0), __ldg(s0 + 16));
    } else {
        int idx = (bid - 4096) * 256 + tid;       // (b*NPAIR + IP)*16 + k
        int k  = idx & 15;
        int ip = (idx >> 4) & (NPAIR - 1);
        int b  = idx >> 15;
        const float* s0 = poses + ((size_t)b * NI + 2 * ip) * 16 + k;
        g_pp[idx] = pack2(__ldg(s0), __ldg(s0 + 16));
    }
}

// ---------------------------------------------------------------------------
// Pass body. Warp owns (batch b, chunk c): lane = o, loops over CP i-pairs.
// Packed over (i0,i1). v (duplicated) lives in shared [k][o] (conflict-free),
// not registers, to keep the hot loop under 128 regs with zero spills.
// ---------------------------------------------------------------------------
template<bool FIRST>
__device__ __forceinline__ void pass_body(int c, int b, int lane,
                                          u64t* PsW, u64t* VdW)
{
    const int o = lane;

    // stage paired poses for (b, chunk c): CP*16 = 256 u64, warp-private
    {
        const u64t* src = g_pp + ((size_t)b * NPAIR + (size_t)c * CP) * 16;
        #pragma unroll
        for (int j = 0; j < 8; j++) PsW[lane + 32 * j] = __ldg(src + lane + 32 * j);
    }
    // stage duplicated v into shared [k][o]
    if (!FIRST) {
        const float4* gv4 = (const float4*)(g_v + ((size_t)b * NO + o) * 16);
        #pragma unroll
        for (int q = 0; q < 4; q++) {
            float4 a = __ldg(gv4 + q);
            VdW[(4 * q + 0) * 32 + o] = pack2d(a.x);
            VdW[(4 * q + 1) * 32 + o] = pack2d(a.y);
            VdW[(4 * q + 2) * 32 + o] = pack2d(a.z);
            VdW[(4 * q + 3) * 32 + o] = pack2d(a.w);
        }
    }
    __syncwarp();

    u64t sacc[16];
    #pragma unroll
    for (int k = 0; k < 16; k++) sacc[k] = 0ull;

    const u64t* Wb = (const u64t*)g_wt2 + (size_t)c * CP * 16 * 32 + o;

    #pragma unroll 1
    for (int ip = 0; ip < CP; ip++) {
        // paired W row: 16 coalesced LDG.64 (L1-hot across the block's warps)
        u64t Wk[16];
        #pragma unroll
        for (int k = 0; k < 16; k++) Wk[k] = __ldg(Wb + (ip * 16 + k) * 32);

        const u64t* Pp = PsW + ip * 16;   // broadcast LDS.64 per pair

        if (FIRST) {
            // votes accumulate straight into sacc (uniform c=1/32 applied in rsB)
            #pragma unroll
            for (int y = 0; y < 4; y++)
                #pragma unroll
                for (int x = 0; x < 4; x++) {
                    u64t p = Pp[x * 4 + y];
                    #pragma unroll
                    for (int z = 0; z < 4; z++)
                        sacc[x * 4 + z] = fma2_(p, Wk[y * 4 + z], sacc[x * 4 + z]);
                }
        } else {
            // votes V[x*4+z] halves = (V_i0, V_i1)
            u64t V[16];
            #pragma unroll
            for (int x = 0; x < 4; x++) {
                u64t p0 = Pp[x * 4];
                #pragma unroll
                for (int z = 0; z < 4; z++) V[x * 4 + z] = mul2_(p0, Wk[z]);
            }
            #pragma unroll
            for (int y = 1; y < 4; y++)
                #pragma unroll
                for (int x = 0; x < 4; x++) {
                    u64t p = Pp[x * 4 + y];
                    #pragma unroll
                    for (int z = 0; z < 4; z++)
                        V[x * 4 + z] = fma2_(p, Wk[y * 4 + z], V[x * 4 + z]);
                }

            // both logits in one packed dot; vd streamed from shared
            u64t da = mul2_(V[0], VdW[0 * 32 + o]);
            u64t db = mul2_(V[1], VdW[1 * 32 + o]);
            #pragma unroll
            for (int k = 2; k < 16; k += 2) {
                da = fma2_(V[k],     VdW[k * 32 + o],       da);
                db = fma2_(V[k + 1], VdW[(k + 1) * 32 + o], db);
            }
            float2 dl = unpack2(add2_(da, db));

            // two independent softmaxes over o (= lanes), interleaved for ILP
            float e0 = __expf(dl.x), e1 = __expf(dl.y);
            float s0 = e0, s1 = e1;
            #pragma unroll
            for (int sh = 16; sh > 0; sh >>= 1) {
                s0 += __shfl_xor_sync(0xffffffffu, s0, sh);
                s1 += __shfl_xor_sync(0xffffffffu, s1, sh);
            }
            u64t cp = pack2(__fdividef(e0, s0), __fdividef(e1, s1));

            #pragma unroll
            for (int k = 0; k < 16; k++) sacc[k] = fma2_(cp, V[k], sacc[k]);
        }
    }

    // writeout: fold the (i0, i1) halves; sole owner of g_part[c][b][o][16]
    float4* gp = (float4*)(g_part + (((size_t)c * NB + b) * NO + o) * 16);
    #pragma unroll
    for (int x = 0; x < 4; x++) {
        float2 a0 = unpack2(sacc[x * 4 + 0]);
        float2 a1 = unpack2(sacc[x * 4 + 1]);
        float2 a2 = unpack2(sacc[x * 4 + 2]);
        float2 a3 = unpack2(sacc[x * 4 + 3]);
        gp[x] = make_float4(a0.x + a0.y, a1.x + a1.y, a2.x + a2.y, a3.x + a3.y);
    }
}

// pass1: no V/vd machinery -> low regs, 5 blocks/SM (20 warps)
__global__ __launch_bounds__(128, 5) void pass1_kernel()
{
    __shared__ u64t Ps[4][CP * 16];   // 8 KB, warp-private slices
    int lane = threadIdx.x & 31, warp = threadIdx.x >> 5;
    pass_body<true>(blockIdx.x, blockIdx.y * 4 + warp, lane, Ps[warp], nullptr);
}

// pass2/3: ~112 regs target, 4 blocks/SM (16 warps), no spills
__global__ __launch_bounds__(128, 4) void pass23_kernel()
{
    __shared__ u64t Ps[4][CP * 16];   // 8 KB
    __shared__ u64t Vd[4][16 * 32];   // 16 KB, [warp][k][o]
    int lane = threadIdx.x & 31, warp = threadIdx.x >> 5;
    pass_body<false>(blockIdx.x, blockIdx.y * 4 + warp, lane, Ps[warp], Vd[warp]);
}

// ---------------------------------------------------------------------------
// rsA: reduce 128 slabs -> 8 partials per element. 131072 threads, coalesced.
// ---------------------------------------------------------------------------
__global__ __launch_bounds__(256) void rsA_kernel()
{
    int idx = blockIdx.x * 256 + threadIdx.x;   // 0 .. 8*EL-1
    int p = idx >> 14;                          // partial group 0..7
    int t = idx & (EL - 1);                     // element
    float s = 0.f;
    const float* gp = g_part + (size_t)(p * 16) * PSLAB + t;
    #pragma unroll
    for (int j = 0; j < 16; j++) s += gp[(size_t)j * PSLAB];
    g_part2[(size_t)p * EL + t] = s;
}

// ---------------------------------------------------------------------------
// rsB: reduce 8 partials + squash. 16384 threads; 16 lanes = one (b,o).
// PHASE 0: v0 -> g_v, g_vsum.  PHASE 1: g_v = v0 + v1.  PHASE 2: write output.
// ---------------------------------------------------------------------------
template<int PHASE>
__global__ __launch_bounds__(256) void rsB_kernel(float* __restrict__ out)
{
    int t = blockIdx.x * 256 + threadIdx.x;     // t = b*512 + o*16 + k
    float s = 0.f;
    #pragma unroll
    for (int p = 0; p < 8; p++) s += g_part2[(size_t)p * EL + t];
    if (PHASE == 0) s *= (1.0f / 32.0f);        // uniform coupling on iter 0

    float n2 = s * s;
    #pragma unroll
    for (int sh = 1; sh < 16; sh <<= 1)
        n2 += __shfl_xor_sync(0xffffffffu, n2, sh);   // sum over 16 pose elems

    float n = sqrtf(n2 + 1e-12f);
    float f = n2 / ((1.0f + n2) * n);
    float v = s * f;

    if (PHASE == 0)      { g_v[t] = v; g_vsum[t] = v; }
    else if (PHASE == 1) { g_v[t] = g_vsum[t] + v; }
    else {
        out[t] = v;                                     // capsule_poses [B,O,4,4]
        if ((t & 15) == 0)
            out[EL + (t >> 4)] = sqrtf(n2 * f * f + 1e-12f);  // activations
    }
}

extern "C" void kernel_launch(void* const* d_in, const int* in_sizes, int n_in,
                              void* d_out, int out_size)
{
    const float* poses = (const float*)d_in[0];
    // d_in[1] = input_activations — unused by the reference math
    const float* w     = (const float*)d_in[2];
    float* out = (float*)d_out;

    dim3 pgrid(NCHUNK, NB / 4);   // 128 x 8 blocks of 128 threads

    prep_kernel<<<8192, 256>>>(poses, w);

    pass1_kernel<<<pgrid, 128>>>();
    rsA_kernel<<<8 * EL / 256, 256>>>();
    rsB_kernel<0><<<EL / 256, 256>>>(nullptr);

    pass23_kernel<<<pgrid, 128>>>();
    rsA_kernel<<<8 * EL / 256, 256>>>();
    rsB_kernel<1><<<EL / 256, 256>>>(nullptr);

    pass23_kernel<<<pgrid, 128>>>();
    rsA_kernel<<<8 * EL / 256, 256>>>();
    rsB_kernel<2><<<EL / 256, 256>>>(out);
}